// round 5
// baseline (speedup 1.0000x reference)
#include <cuda_runtime.h>

#define S_LEN 2048
#define BATCH 4
#define HEADS 16
#define DH 64
#define DIN 1024
#define M_TOT (BATCH * S_LEN)  // 8192

// ---------------- scratch (allocation-free) ----------------
__device__ float g_q[BATCH * HEADS * S_LEN * DH];   // [B,H,S,64] fp32
__device__ float g_k[BATCH * HEADS * S_LEN * DH];
__device__ float g_v[BATCH * HEADS * S_LEN * DH];
__device__ float g_attn[M_TOT * HEADS * DH];        // [m][h*64+e] fp32

// ---------------- helpers ----------------
__device__ __forceinline__ unsigned f2tf(float f) {
    unsigned r;
    asm("cvt.rna.tf32.f32 %0, %1;" : "=r"(r) : "f"(f));
    return r;
}
__device__ __forceinline__ void mma_tf32(float* c, unsigned a0, unsigned a1,
                                         unsigned a2, unsigned a3,
                                         unsigned b0, unsigned b1) {
    asm volatile(
        "mma.sync.aligned.m16n8k8.row.col.f32.tf32.tf32.f32 "
        "{%0,%1,%2,%3}, {%4,%5,%6,%7}, {%8,%9}, {%0,%1,%2,%3};\n"
        : "+f"(c[0]), "+f"(c[1]), "+f"(c[2]), "+f"(c[3])
        : "r"(a0), "r"(a1), "r"(a2), "r"(a3), "r"(b0), "r"(b1));
}
__device__ __forceinline__ void cp16(unsigned saddr, const void* gptr) {
    asm volatile("cp.async.ca.shared.global [%0], [%1], 16;\n"
                 :: "r"(saddr), "l"(gptr));
}
__device__ __forceinline__ unsigned saddr_of(const void* p) {
    return (unsigned)__cvta_generic_to_shared(p);
}
#define CP_COMMIT() asm volatile("cp.async.commit_group;\n" ::: "memory")
#define CP_WAIT1()  asm volatile("cp.async.wait_group 1;\n" ::: "memory")
#define CP_WAIT0()  asm volatile("cp.async.wait_group 0;\n" ::: "memory")

// ======================= QKV projection (cp.async pipelined tf32 MMA) ============
// grid (64 m-tiles, 8 head-pairs, 3); block 256 (8 warps 4M x 2N), warp 32x64.
// fp32 tiles in smem (double-buffered via cp.async), cvt->tf32 at fragment load.
#define QBM 128
#define QBK 32
#define ASTR 36      // == 4 mod 32: A frag bank 4g+t, conflict-free
#define BSTR 136     // == 8 mod 32: B frag bank 8t+g, conflict-free
#define QA_W (QBM * ASTR)   // 4608 floats
#define QB_W (QBK * BSTR)   // 4352
#define QKV_SMEM ((QA_W + QB_W) * 2 * 4)  // 71680 B

__global__ __launch_bounds__(256, 2) void qkv_gemm(
    const float* __restrict__ x,
    const float* __restrict__ Wq, const float* __restrict__ bq,
    const float* __restrict__ Wk, const float* __restrict__ bk,
    const float* __restrict__ Wv, const float* __restrict__ bv)
{
    extern __shared__ float qsm[];
    float* As = qsm;                 // [2][128][36]
    float* Bs = qsm + 2 * QA_W;      // [2][32][136]

    const int p = blockIdx.z, hp = blockIdx.y;
    const float* W; const float* bias; float* out;
    if (p == 0)      { W = Wq; bias = bq; out = g_q; }
    else if (p == 1) { W = Wk; bias = bk; out = g_k; }
    else             { W = Wv; bias = bv; out = g_v; }
    const float* W0 = W + (size_t)(2 * hp) * DIN * DH;

    const int tid = threadIdx.x, w = tid >> 5, lane = tid & 31;
    const int g = lane >> 2, t = lane & 3;
    const int wm = w >> 1, wn = w & 1;
    const int m0 = blockIdx.x * QBM;

    const int la_r = tid >> 3, la_c = (tid & 7) * 4;   // A: 32 rows x 4 passes
    const int lb_r = tid >> 5, lb_n = (tid & 31) * 4;  // B: 8 rows x 4 passes
    const float* xA = x + (size_t)(m0 + la_r) * DIN + la_c;
    const float* WB = W0 + (size_t)(lb_n >> 6) * DIN * DH + (lb_n & 63);

    auto issue = [&](int k0, int buf) {
        float* Aw = As + buf * QA_W;
        float* Bw = Bs + buf * QB_W;
        #pragma unroll
        for (int it = 0; it < 4; it++)
            cp16(saddr_of(&Aw[(la_r + 32 * it) * ASTR + la_c]),
                 xA + k0 + (size_t)(32 * it) * DIN);
        #pragma unroll
        for (int it = 0; it < 4; it++)
            cp16(saddr_of(&Bw[(lb_r + 8 * it) * BSTR + lb_n]),
                 WB + (size_t)(k0 + lb_r + 8 * it) * DH);
        CP_COMMIT();
    };

    float acc[2][8][4] = {};
    const int NT = DIN / QBK;  // 32

    issue(0, 0);
    for (int tt = 0; tt < NT; tt++) {
        if (tt + 1 < NT) issue((tt + 1) * QBK, (tt + 1) & 1);
        if (tt + 1 < NT) { CP_WAIT1(); } else { CP_WAIT0(); }
        __syncthreads();

        const float* Ab = As + (tt & 1) * QA_W;
        const float* Bb = Bs + (tt & 1) * QB_W;
        #pragma unroll
        for (int ks = 0; ks < 4; ks++) {
            unsigned a[2][4];
            #pragma unroll
            for (int mi = 0; mi < 2; mi++) {
                int r0 = (32 * wm + 16 * mi + g) * ASTR + 8 * ks;
                int r1 = r0 + 8 * ASTR;
                a[mi][0] = f2tf(Ab[r0 + t]);     a[mi][1] = f2tf(Ab[r1 + t]);
                a[mi][2] = f2tf(Ab[r0 + t + 4]); a[mi][3] = f2tf(Ab[r1 + t + 4]);
            }
            #pragma unroll
            for (int nf = 0; nf < 8; nf++) {
                int n = 64 * wn + 8 * nf + g;
                unsigned b0 = f2tf(Bb[(8 * ks + t) * BSTR + n]);
                unsigned b1 = f2tf(Bb[(8 * ks + t + 4) * BSTR + n]);
                mma_tf32(acc[0][nf], a[0][0], a[0][1], a[0][2], a[0][3], b0, b1);
                mma_tf32(acc[1][nf], a[1][0], a[1][1], a[1][2], a[1][3], b0, b1);
            }
        }
        __syncthreads();
    }

    // epilogue: bias + scatter to [B,H,S,64]
    const int head = 2 * hp + wn;
    const float* bp = bias + head * DH;
    #pragma unroll
    for (int mi = 0; mi < 2; mi++) {
        #pragma unroll
        for (int nf = 0; nf < 8; nf++) {
            int e = 8 * nf + 2 * t;
            float be0 = bp[e], be1 = bp[e + 1];
            int row = m0 + 32 * wm + 16 * mi + g;
            #pragma unroll
            for (int rr = 0; rr < 2; rr++) {
                int m = row + 8 * rr;
                int bb = m >> 11, s = m & 2047;
                size_t base = (((size_t)bb * HEADS + head) * S_LEN + s) * DH + e;
                *(float2*)(out + base) =
                    make_float2(acc[mi][nf][2 * rr] + be0,
                                acc[mi][nf][2 * rr + 1] + be1);
            }
        }
    }
}

// ======================= Flash attention (cp.async pipelined tf32 MMA) ===========
// grid (16 q-tiles, 64 bh); block 128 (4 warps x 32 q-rows). KV tile 64, dbl-buf.
// K/V fp32 in smem (cvt at frag load); Q frags register-resident; P tf32 in smem.
#define FK 68    // == 4 mod 32
#define FV 72    // == 8 mod 32
#define FP 68
#define K_W (64 * FK)    // 4352 floats
#define V_W (64 * FV)    // 4608
#define P_W (128 * FP)   // 8704 (tf32 words)
#define ATT_SMEM (((K_W + V_W) * 2 + P_W) * 4)  // 106496 B

__global__ __launch_bounds__(128, 1) void flash_kernel()
{
    extern __shared__ float fsm[];
    float* Ks = fsm;                       // [2][64][68]
    float* Vs = fsm + 2 * K_W;             // [2][64][72]
    unsigned* Ps = (unsigned*)(fsm + 2 * (K_W + V_W));  // [128][68] tf32; Q staging

    const int tid = threadIdx.x, w = tid >> 5, lane = tid & 31;
    const int g = lane >> 2, t = lane & 3;
    const int qt = (int)(gridDim.x - 1 - blockIdx.x);   // big tiles first
    const int bh = blockIdx.y;
    const size_t base = (size_t)bh * S_LEN * DH;
    const int qrow0 = qt * 128;

    const int lkv_r = tid >> 1, lkv_c = (tid & 1) * 32;  // 64 rows, 2 half-rows
    auto issue_kv = [&](int kt, int buf) {
        float* Kw = Ks + buf * K_W;
        float* Vw = Vs + buf * V_W;
        const float* kg = g_k + base + (size_t)(kt * 64 + lkv_r) * DH + lkv_c;
        const float* vg = g_v + base + (size_t)(kt * 64 + lkv_r) * DH + lkv_c;
        #pragma unroll
        for (int i = 0; i < 8; i++)
            cp16(saddr_of(&Kw[lkv_r * FK + lkv_c + 4 * i]), kg + 4 * i);
        #pragma unroll
        for (int i = 0; i < 8; i++)
            cp16(saddr_of(&Vw[lkv_r * FV + lkv_c + 4 * i]), vg + 4 * i);
        CP_COMMIT();
    };

    issue_kv(0, 0);   // overlap with Q staging below

    // stage Q (128x64) into Ps with 1/8 scale folded, then hoist frags to regs
    #pragma unroll
    for (int i = 0; i < 16; i++) {
        int slot = tid + i * 128;
        int row = slot >> 4, c = (slot & 15) * 4;
        float4 v = *(const float4*)(g_q + base + (size_t)(qrow0 + row) * DH + c);
        *(uint4*)&Ps[row * FP + c] = make_uint4(
            f2tf(v.x * 0.125f), f2tf(v.y * 0.125f),
            f2tf(v.z * 0.125f), f2tf(v.w * 0.125f));
    }
    __syncthreads();
    unsigned qf[2][8][4];
    #pragma unroll
    for (int mi = 0; mi < 2; mi++)
        #pragma unroll
        for (int ks = 0; ks < 8; ks++) {
            int r0 = (32 * w + 16 * mi + g) * FP + 8 * ks;
            int r1 = r0 + 8 * FP;
            qf[mi][ks][0] = Ps[r0 + t];     qf[mi][ks][1] = Ps[r1 + t];
            qf[mi][ks][2] = Ps[r0 + t + 4]; qf[mi][ks][3] = Ps[r1 + t + 4];
        }

    float m_i[4] = {-1e30f, -1e30f, -1e30f, -1e30f};
    float l_i[4] = {0.f, 0.f, 0.f, 0.f};
    float o[2][8][4] = {};

    const int ktmax = 2 * qt + 1;
    for (int kt = 0; kt <= ktmax; kt++) {
        if (kt < ktmax) issue_kv(kt + 1, (kt + 1) & 1);
        if (kt < ktmax) { CP_WAIT1(); } else { CP_WAIT0(); }
        __syncthreads();
        const float* Kb = Ks + (kt & 1) * K_W;
        const float* Vb = Vs + (kt & 1) * V_W;

        // S = Q K^T
        float c_[2][8][4] = {};
        #pragma unroll
        for (int ks = 0; ks < 8; ks++) {
            #pragma unroll
            for (int nf = 0; nf < 8; nf++) {
                unsigned b0 = f2tf(Kb[(8 * nf + g) * FK + 8 * ks + t]);
                unsigned b1 = f2tf(Kb[(8 * nf + g) * FK + 8 * ks + t + 4]);
                mma_tf32(c_[0][nf], qf[0][ks][0], qf[0][ks][1], qf[0][ks][2], qf[0][ks][3], b0, b1);
                mma_tf32(c_[1][nf], qf[1][ks][0], qf[1][ks][1], qf[1][ks][2], qf[1][ks][3], b0, b1);
            }
        }

        // causal mask (only the two diagonal-adjacent kv tiles)
        if (kt >= 2 * qt) {
            int colbase = kt * 64;
            #pragma unroll
            for (int mi = 0; mi < 2; mi++) {
                int r0 = qrow0 + 32 * w + 16 * mi + g;
                #pragma unroll
                for (int nf = 0; nf < 8; nf++) {
                    int col = colbase + 8 * nf + 2 * t;
                    if (col     > r0)     c_[mi][nf][0] = -1e30f;
                    if (col + 1 > r0)     c_[mi][nf][1] = -1e30f;
                    if (col     > r0 + 8) c_[mi][nf][2] = -1e30f;
                    if (col + 1 > r0 + 8) c_[mi][nf][3] = -1e30f;
                }
            }
        }

        // online softmax: 4 rows/thread
        float alpha[4];
        #pragma unroll
        for (int mi = 0; mi < 2; mi++)
            #pragma unroll
            for (int hh = 0; hh < 2; hh++) {
                int rr = 2 * mi + hh;
                float mx = -1e30f;
                #pragma unroll
                for (int nf = 0; nf < 8; nf++)
                    mx = fmaxf(mx, fmaxf(c_[mi][nf][2 * hh], c_[mi][nf][2 * hh + 1]));
                mx = fmaxf(mx, __shfl_xor_sync(0xffffffffu, mx, 1));
                mx = fmaxf(mx, __shfl_xor_sync(0xffffffffu, mx, 2));
                float m_new = fmaxf(m_i[rr], mx);
                alpha[rr] = __expf(m_i[rr] - m_new);
                float sum = 0.f;
                #pragma unroll
                for (int nf = 0; nf < 8; nf++) {
                    float p0 = __expf(c_[mi][nf][2 * hh] - m_new);
                    float p1 = __expf(c_[mi][nf][2 * hh + 1] - m_new);
                    c_[mi][nf][2 * hh] = p0; c_[mi][nf][2 * hh + 1] = p1;
                    sum += p0 + p1;
                }
                sum += __shfl_xor_sync(0xffffffffu, sum, 1);
                sum += __shfl_xor_sync(0xffffffffu, sum, 2);
                l_i[rr] = l_i[rr] * alpha[rr] + sum;
                m_i[rr] = m_new;
            }

        // stage P (warp-private rows) + rescale O
        #pragma unroll
        for (int mi = 0; mi < 2; mi++) {
            int pr = (32 * w + 16 * mi + g) * FP;
            #pragma unroll
            for (int nf = 0; nf < 8; nf++) {
                int col = 8 * nf + 2 * t;
                *(uint2*)&Ps[pr + col] =
                    make_uint2(f2tf(c_[mi][nf][0]), f2tf(c_[mi][nf][1]));
                *(uint2*)&Ps[pr + 8 * FP + col] =
                    make_uint2(f2tf(c_[mi][nf][2]), f2tf(c_[mi][nf][3]));
            }
        }
        #pragma unroll
        for (int mi = 0; mi < 2; mi++)
            #pragma unroll
            for (int nf = 0; nf < 8; nf++) {
                o[mi][nf][0] *= alpha[2 * mi];     o[mi][nf][1] *= alpha[2 * mi];
                o[mi][nf][2] *= alpha[2 * mi + 1]; o[mi][nf][3] *= alpha[2 * mi + 1];
            }
        __syncwarp();

        // O += P V
        #pragma unroll
        for (int ks = 0; ks < 8; ks++) {
            unsigned a[2][4];
            #pragma unroll
            for (int mi = 0; mi < 2; mi++) {
                int r0 = (32 * w + 16 * mi + g) * FP + 8 * ks;
                int r1 = r0 + 8 * FP;
                a[mi][0] = Ps[r0 + t];     a[mi][1] = Ps[r1 + t];
                a[mi][2] = Ps[r0 + t + 4]; a[mi][3] = Ps[r1 + t + 4];
            }
            #pragma unroll
            for (int nf = 0; nf < 8; nf++) {
                unsigned b0 = f2tf(Vb[(8 * ks + t) * FV + 8 * nf + g]);
                unsigned b1 = f2tf(Vb[(8 * ks + t + 4) * FV + 8 * nf + g]);
                mma_tf32(o[0][nf], a[0][0], a[0][1], a[0][2], a[0][3], b0, b1);
                mma_tf32(o[1][nf], a[1][0], a[1][1], a[1][2], a[1][3], b0, b1);
            }
        }
        __syncthreads();   // K/V buffer + P reuse guard
    }

    // epilogue: normalize + concat-head write [m][h*64+e]
    const int b = bh >> 4, h = bh & 15;
    #pragma unroll
    for (int mi = 0; mi < 2; mi++) {
        float inv0 = 1.f / l_i[2 * mi], inv1 = 1.f / l_i[2 * mi + 1];
        int row = qrow0 + 32 * w + 16 * mi + g;
        #pragma unroll
        for (int nf = 0; nf < 8; nf++) {
            int e = 8 * nf + 2 * t;
            size_t i0 = ((size_t)(b * S_LEN + row)) * (HEADS * DH) + h * DH + e;
            size_t i1 = ((size_t)(b * S_LEN + row + 8)) * (HEADS * DH) + h * DH + e;
            *(float2*)(g_attn + i0) = make_float2(o[mi][nf][0] * inv0, o[mi][nf][1] * inv0);
            *(float2*)(g_attn + i1) = make_float2(o[mi][nf][2] * inv1, o[mi][nf][3] * inv1);
        }
    }
}

// ======================= Output projection (tf32 MMA) =======================
#define OBM 128
#define OBK 32
#define OASTR 36
#define OBSTR 72

__global__ __launch_bounds__(256) void out_gemm(
    const float* __restrict__ Wo, const float* __restrict__ bo,
    float* __restrict__ outp)
{
    __shared__ float As[OBM * OASTR];
    __shared__ float Bs[OBK * OBSTR];

    const int tid = threadIdx.x, w = tid >> 5, lane = tid & 31;
    const int g = lane >> 2, t = lane & 3;
    const int wm = w >> 1, wn = w & 1;
    const int m0 = blockIdx.x * OBM;

    float acc[2][4][4] = {};

    for (int k0 = 0; k0 < DIN; k0 += OBK) {
        __syncthreads();
        {
            int r = tid >> 3, kc = (tid & 7) * 4;
            #pragma unroll
            for (int it = 0; it < 4; it++) {
                int row = r + 32 * it;
                *(float4*)&As[row * OASTR + kc] =
                    *(const float4*)(g_attn + (size_t)(m0 + row) * DIN + k0 + kc);
            }
        }
        {
            int r = tid >> 4, n = (tid & 15) * 4;
            #pragma unroll
            for (int it = 0; it < 2; it++) {
                int row = r + 16 * it;
                *(float4*)&Bs[row * OBSTR + n] =
                    *(const float4*)(Wo + (size_t)(k0 + row) * DH + n);
            }
        }
        __syncthreads();

        #pragma unroll
        for (int ks = 0; ks < 4; ks++) {
            unsigned a[2][4];
            #pragma unroll
            for (int mi = 0; mi < 2; mi++) {
                int r0 = (32 * wm + 16 * mi + g) * OASTR + 8 * ks;
                int r1 = r0 + 8 * OASTR;
                a[mi][0] = f2tf(As[r0 + t]);     a[mi][1] = f2tf(As[r1 + t]);
                a[mi][2] = f2tf(As[r0 + t + 4]); a[mi][3] = f2tf(As[r1 + t + 4]);
            }
            #pragma unroll
            for (int nf = 0; nf < 4; nf++) {
                int n = 32 * wn + 8 * nf + g;
                unsigned b0 = f2tf(Bs[(8 * ks + t) * OBSTR + n]);
                unsigned b1 = f2tf(Bs[(8 * ks + t + 4) * OBSTR + n]);
                mma_tf32(acc[0][nf], a[0][0], a[0][1], a[0][2], a[0][3], b0, b1);
                mma_tf32(acc[1][nf], a[1][0], a[1][1], a[1][2], a[1][3], b0, b1);
            }
        }
    }

    #pragma unroll
    for (int mi = 0; mi < 2; mi++)
        #pragma unroll
        for (int nf = 0; nf < 4; nf++) {
            int e = 32 * wn + 8 * nf + 2 * t;
            float be0 = bo[e], be1 = bo[e + 1];
            int row = m0 + 32 * wm + 16 * mi + g;
            #pragma unroll
            for (int rr = 0; rr < 2; rr++) {
                int m = row + 8 * rr;
                *(float2*)(outp + (size_t)m * DH + e) =
                    make_float2(acc[mi][nf][2 * rr] + be0,
                                acc[mi][nf][2 * rr + 1] + be1);
            }
        }
}

// ======================= launch =======================
extern "C" void kernel_launch(void* const* d_in, const int* in_sizes, int n_in,
                              void* d_out, int out_size)
{
    const float* x  = (const float*)d_in[0];
    const float* Wq = (const float*)d_in[1];
    const float* bq = (const float*)d_in[2];
    const float* Wk = (const float*)d_in[3];
    const float* bk = (const float*)d_in[4];
    const float* Wv = (const float*)d_in[5];
    const float* bv = (const float*)d_in[6];
    const float* Wo = (const float*)d_in[7];
    const float* bo = (const float*)d_in[8];
    float* outp = (float*)d_out;

    cudaFuncSetAttribute(qkv_gemm,
                         cudaFuncAttributeMaxDynamicSharedMemorySize, QKV_SMEM);
    cudaFuncSetAttribute(flash_kernel,
                         cudaFuncAttributeMaxDynamicSharedMemorySize, ATT_SMEM);

    dim3 g1(M_TOT / QBM, HEADS / 2, 3);
    qkv_gemm<<<g1, 256, QKV_SMEM>>>(x, Wq, bq, Wk, bk, Wv, bv);

    dim3 g2(S_LEN / 128, BATCH * HEADS);
    flash_kernel<<<g2, 128, ATT_SMEM>>>();

    out_gemm<<<M_TOT / OBM, 256>>>(Wo, bo, outp);
}

// round 6
// speedup vs baseline: 1.0675x; 1.0675x over previous
#include <cuda_runtime.h>

#define S_LEN 2048
#define BATCH 4
#define HEADS 16
#define DH 64
#define DIN 1024
#define M_TOT (BATCH * S_LEN)  // 8192

// ---------------- scratch (allocation-free) — tf32 words ----------------
__device__ unsigned g_xt[M_TOT * DIN];               // x as tf32
__device__ unsigned g_wq[HEADS * DIN * DH];          // weights as tf32
__device__ unsigned g_wk[HEADS * DIN * DH];
__device__ unsigned g_wv[HEADS * DIN * DH];
__device__ unsigned g_wo[DIN * DH];
__device__ unsigned g_q[BATCH * HEADS * S_LEN * DH]; // tf32, 1/8 scale folded
__device__ unsigned g_k[BATCH * HEADS * S_LEN * DH];
__device__ unsigned g_v[BATCH * HEADS * S_LEN * DH];
__device__ unsigned g_attn[M_TOT * HEADS * DH];      // [m][h*64+e] tf32

// ---------------- helpers ----------------
__device__ __forceinline__ unsigned f2tf(float f) {
    unsigned r;
    asm("cvt.rna.tf32.f32 %0, %1;" : "=r"(r) : "f"(f));
    return r;
}
__device__ __forceinline__ void mma_tf32(float* c, unsigned a0, unsigned a1,
                                         unsigned a2, unsigned a3,
                                         unsigned b0, unsigned b1) {
    asm volatile(
        "mma.sync.aligned.m16n8k8.row.col.f32.tf32.tf32.f32 "
        "{%0,%1,%2,%3}, {%4,%5,%6,%7}, {%8,%9}, {%0,%1,%2,%3};\n"
        : "+f"(c[0]), "+f"(c[1]), "+f"(c[2]), "+f"(c[3])
        : "r"(a0), "r"(a1), "r"(a2), "r"(a3), "r"(b0), "r"(b1));
}
__device__ __forceinline__ void cp16(unsigned saddr, const void* gptr) {
    asm volatile("cp.async.ca.shared.global [%0], [%1], 16;\n"
                 :: "r"(saddr), "l"(gptr));
}
__device__ __forceinline__ unsigned saddr_of(const void* p) {
    return (unsigned)__cvta_generic_to_shared(p);
}
#define CP_COMMIT() asm volatile("cp.async.commit_group;\n" ::: "memory")
#define CP_WAIT0()  asm volatile("cp.async.wait_group 0;\n" ::: "memory")

// ======================= tf32 pre-convert =======================
__global__ __launch_bounds__(256) void to_tf32_kernel(
    const float4* __restrict__ src, uint4* __restrict__ dst, int n4)
{
    int i = blockIdx.x * blockDim.x + threadIdx.x;
    if (i < n4) {
        float4 v = src[i];
        dst[i] = make_uint4(f2tf(v.x), f2tf(v.y), f2tf(v.z), f2tf(v.w));
    }
}

// ======================= QKV projection =======================
// grid (64 m-tiles, 8 head-pairs, 3); block 128 (4 warps = 2M x 2N), warp 64x64.
// Block tile 128M x 128N (two heads). tf32 tiles, cp.async double-buffered.
#define QBM 128
#define QBK 32
#define ASTR 36      // == 4 mod 32: A frag bank 4g+t, conflict-free
#define BSTR 136     // == 8 mod 32: B frag bank 8t+g, conflict-free
#define QA_W (QBM * ASTR)   // 4608
#define QB_W (QBK * BSTR)   // 4352
#define QKV_SMEM ((QA_W + QB_W) * 2 * 4)  // 71680 B

__global__ __launch_bounds__(128, 2) void qkv_gemm(
    const float* __restrict__ bq, const float* __restrict__ bk,
    const float* __restrict__ bv)
{
    extern __shared__ unsigned qsm[];
    unsigned* As = qsm;                 // [2][128][36]
    unsigned* Bs = qsm + 2 * QA_W;      // [2][32][136]

    const int p = blockIdx.z, hp = blockIdx.y;
    const unsigned* W; const float* bias; unsigned* out; float sc;
    if (p == 0)      { W = g_wq; bias = bq; out = g_q; sc = 0.125f; }
    else if (p == 1) { W = g_wk; bias = bk; out = g_k; sc = 1.0f; }
    else             { W = g_wv; bias = bv; out = g_v; sc = 1.0f; }
    const unsigned* W0 = W + (size_t)(2 * hp) * DIN * DH;

    const int tid = threadIdx.x, w = tid >> 5, lane = tid & 31;
    const int g = lane >> 2, t = lane & 3;
    const int wm = w >> 1, wn = w & 1;
    const int m0 = blockIdx.x * QBM;

    const int la_r = tid >> 3, la_c = (tid & 7) * 4;   // A: 16 rows x 8 passes
    const int lb_r = tid >> 5, lb_n = (tid & 31) * 4;  // B: 4 rows x 8 passes
    const unsigned* xA = g_xt + (size_t)(m0 + la_r) * DIN + la_c;
    const unsigned* WB = W0 + (size_t)(lb_n >> 6) * DIN * DH + (lb_n & 63);

    auto issue = [&](int k0, int buf) {
        unsigned* Aw = As + buf * QA_W;
        unsigned* Bw = Bs + buf * QB_W;
        #pragma unroll
        for (int it = 0; it < 8; it++)
            cp16(saddr_of(&Aw[(la_r + 16 * it) * ASTR + la_c]),
                 xA + k0 + (size_t)(16 * it) * DIN);
        #pragma unroll
        for (int it = 0; it < 8; it++)
            cp16(saddr_of(&Bw[(lb_r + 4 * it) * BSTR + lb_n]),
                 WB + (size_t)(k0 + lb_r + 4 * it) * DH);
        CP_COMMIT();
    };

    float acc[4][8][4] = {};
    const int NT = DIN / QBK;  // 32

    issue(0, 0);
    for (int tt = 0; tt < NT; tt++) {
        CP_WAIT0();
        __syncthreads();            // tile tt ready; all warps done with tt-1
        if (tt + 1 < NT) issue((tt + 1) * QBK, (tt + 1) & 1);

        const unsigned* Ab = As + (tt & 1) * QA_W;
        const unsigned* Bb = Bs + (tt & 1) * QB_W;
        #pragma unroll
        for (int ks = 0; ks < 4; ks++) {
            unsigned a[4][4];
            #pragma unroll
            for (int mi = 0; mi < 4; mi++) {
                int r0 = (64 * wm + 16 * mi + g) * ASTR + 8 * ks;
                int r1 = r0 + 8 * ASTR;
                a[mi][0] = Ab[r0 + t];     a[mi][1] = Ab[r1 + t];
                a[mi][2] = Ab[r0 + t + 4]; a[mi][3] = Ab[r1 + t + 4];
            }
            #pragma unroll
            for (int nf = 0; nf < 8; nf++) {
                int n = 64 * wn + 8 * nf + g;
                unsigned b0 = Bb[(8 * ks + t) * BSTR + n];
                unsigned b1 = Bb[(8 * ks + t + 4) * BSTR + n];
                #pragma unroll
                for (int mi = 0; mi < 4; mi++)
                    mma_tf32(acc[mi][nf], a[mi][0], a[mi][1], a[mi][2], a[mi][3], b0, b1);
            }
        }
    }

    // epilogue: bias (+Q scale) -> tf32 -> scatter to [B,H,S,64]
    const int head = 2 * hp + wn;
    const float* bp = bias + head * DH;
    #pragma unroll
    for (int mi = 0; mi < 4; mi++) {
        #pragma unroll
        for (int nf = 0; nf < 8; nf++) {
            int e = 8 * nf + 2 * t;
            float be0 = bp[e], be1 = bp[e + 1];
            int row = m0 + 64 * wm + 16 * mi + g;
            #pragma unroll
            for (int rr = 0; rr < 2; rr++) {
                int m = row + 8 * rr;
                int bb = m >> 11, s = m & 2047;
                size_t base = (((size_t)bb * HEADS + head) * S_LEN + s) * DH + e;
                *(uint2*)(out + base) = make_uint2(
                    f2tf((acc[mi][nf][2 * rr] + be0) * sc),
                    f2tf((acc[mi][nf][2 * rr + 1] + be1) * sc));
            }
        }
    }
}

// ======================= Flash attention =======================
// grid (16 q-tiles, 64 bh); block 128 (4 warps x 32 q-rows). KV tile 64, dbl-buf.
// All operands already tf32: zero cvt in the QK^T / PV loops.
#define FK 68    // == 4 mod 32
#define FV 72    // == 8 mod 32
#define FP 68
#define K_W (64 * FK)    // 4352
#define V_W (64 * FV)    // 4608
#define P_W (128 * FP)   // 8704
#define ATT_SMEM (((K_W + V_W) * 2 + P_W) * 4)  // 106496 B

__global__ __launch_bounds__(128, 2) void flash_kernel()
{
    extern __shared__ unsigned fsm[];
    unsigned* Ks = fsm;                    // [2][64][68]
    unsigned* Vs = fsm + 2 * K_W;          // [2][64][72]
    unsigned* Ps = fsm + 2 * (K_W + V_W);  // [128][68]; also Q staging

    const int tid = threadIdx.x, w = tid >> 5, lane = tid & 31;
    const int g = lane >> 2, t = lane & 3;
    const int qt = (int)(gridDim.x - 1 - blockIdx.x);   // big tiles first
    const int bh = blockIdx.y;
    const size_t base = (size_t)bh * S_LEN * DH;
    const int qrow0 = qt * 128;

    const int lkv_r = tid >> 1, lkv_c = (tid & 1) * 32;
    auto issue_kv = [&](int kt, int buf) {
        unsigned* Kw = Ks + buf * K_W;
        unsigned* Vw = Vs + buf * V_W;
        const unsigned* kg = g_k + base + (size_t)(kt * 64 + lkv_r) * DH + lkv_c;
        const unsigned* vg = g_v + base + (size_t)(kt * 64 + lkv_r) * DH + lkv_c;
        #pragma unroll
        for (int i = 0; i < 8; i++)
            cp16(saddr_of(&Kw[lkv_r * FK + lkv_c + 4 * i]), kg + 4 * i);
        #pragma unroll
        for (int i = 0; i < 8; i++)
            cp16(saddr_of(&Vw[lkv_r * FV + lkv_c + 4 * i]), vg + 4 * i);
        CP_COMMIT();
    };

    issue_kv(0, 0);

    // stage Q (already tf32, scale folded) and hoist fragments
    #pragma unroll
    for (int i = 0; i < 16; i++) {
        int slot = tid + i * 128;
        int row = slot >> 4, c = (slot & 15) * 4;
        *(uint4*)&Ps[row * FP + c] =
            *(const uint4*)(g_q + base + (size_t)(qrow0 + row) * DH + c);
    }
    __syncthreads();
    unsigned qf[2][8][4];
    #pragma unroll
    for (int mi = 0; mi < 2; mi++)
        #pragma unroll
        for (int ks = 0; ks < 8; ks++) {
            int r0 = (32 * w + 16 * mi + g) * FP + 8 * ks;
            int r1 = r0 + 8 * FP;
            qf[mi][ks][0] = Ps[r0 + t];     qf[mi][ks][1] = Ps[r1 + t];
            qf[mi][ks][2] = Ps[r0 + t + 4]; qf[mi][ks][3] = Ps[r1 + t + 4];
        }

    float m_i[4] = {-1e30f, -1e30f, -1e30f, -1e30f};
    float l_i[4] = {0.f, 0.f, 0.f, 0.f};
    float o[2][8][4] = {};

    const int ktmax = 2 * qt + 1;
    for (int kt = 0; kt <= ktmax; kt++) {
        CP_WAIT0();
        __syncthreads();            // kt data ready; all warps done with kt-1
        if (kt < ktmax) issue_kv(kt + 1, (kt + 1) & 1);
        const unsigned* Kb = Ks + (kt & 1) * K_W;
        const unsigned* Vb = Vs + (kt & 1) * V_W;

        // S = Q K^T
        float c_[2][8][4] = {};
        #pragma unroll
        for (int ks = 0; ks < 8; ks++) {
            #pragma unroll
            for (int nf = 0; nf < 8; nf++) {
                unsigned b0 = Kb[(8 * nf + g) * FK + 8 * ks + t];
                unsigned b1 = Kb[(8 * nf + g) * FK + 8 * ks + t + 4];
                mma_tf32(c_[0][nf], qf[0][ks][0], qf[0][ks][1], qf[0][ks][2], qf[0][ks][3], b0, b1);
                mma_tf32(c_[1][nf], qf[1][ks][0], qf[1][ks][1], qf[1][ks][2], qf[1][ks][3], b0, b1);
            }
        }

        // causal mask (diagonal-adjacent tiles only)
        if (kt >= 2 * qt) {
            int colbase = kt * 64;
            #pragma unroll
            for (int mi = 0; mi < 2; mi++) {
                int r0 = qrow0 + 32 * w + 16 * mi + g;
                #pragma unroll
                for (int nf = 0; nf < 8; nf++) {
                    int col = colbase + 8 * nf + 2 * t;
                    if (col     > r0)     c_[mi][nf][0] = -1e30f;
                    if (col + 1 > r0)     c_[mi][nf][1] = -1e30f;
                    if (col     > r0 + 8) c_[mi][nf][2] = -1e30f;
                    if (col + 1 > r0 + 8) c_[mi][nf][3] = -1e30f;
                }
            }
        }

        // online softmax: 4 rows/thread
        float alpha[4];
        #pragma unroll
        for (int mi = 0; mi < 2; mi++)
            #pragma unroll
            for (int hh = 0; hh < 2; hh++) {
                int rr = 2 * mi + hh;
                float mx = -1e30f;
                #pragma unroll
                for (int nf = 0; nf < 8; nf++)
                    mx = fmaxf(mx, fmaxf(c_[mi][nf][2 * hh], c_[mi][nf][2 * hh + 1]));
                mx = fmaxf(mx, __shfl_xor_sync(0xffffffffu, mx, 1));
                mx = fmaxf(mx, __shfl_xor_sync(0xffffffffu, mx, 2));
                float m_new = fmaxf(m_i[rr], mx);
                alpha[rr] = __expf(m_i[rr] - m_new);
                float sum = 0.f;
                #pragma unroll
                for (int nf = 0; nf < 8; nf++) {
                    float p0 = __expf(c_[mi][nf][2 * hh] - m_new);
                    float p1 = __expf(c_[mi][nf][2 * hh + 1] - m_new);
                    c_[mi][nf][2 * hh] = p0; c_[mi][nf][2 * hh + 1] = p1;
                    sum += p0 + p1;
                }
                sum += __shfl_xor_sync(0xffffffffu, sum, 1);
                sum += __shfl_xor_sync(0xffffffffu, sum, 2);
                l_i[rr] = l_i[rr] * alpha[rr] + sum;
                m_i[rr] = m_new;
            }

        // stage P (warp-private rows) + rescale O
        #pragma unroll
        for (int mi = 0; mi < 2; mi++) {
            int pr = (32 * w + 16 * mi + g) * FP;
            #pragma unroll
            for (int nf = 0; nf < 8; nf++) {
                int col = 8 * nf + 2 * t;
                *(uint2*)&Ps[pr + col] =
                    make_uint2(f2tf(c_[mi][nf][0]), f2tf(c_[mi][nf][1]));
                *(uint2*)&Ps[pr + 8 * FP + col] =
                    make_uint2(f2tf(c_[mi][nf][2]), f2tf(c_[mi][nf][3]));
            }
        }
        #pragma unroll
        for (int mi = 0; mi < 2; mi++)
            #pragma unroll
            for (int nf = 0; nf < 8; nf++) {
                o[mi][nf][0] *= alpha[2 * mi];     o[mi][nf][1] *= alpha[2 * mi];
                o[mi][nf][2] *= alpha[2 * mi + 1]; o[mi][nf][3] *= alpha[2 * mi + 1];
            }
        __syncwarp();

        // O += P V
        #pragma unroll
        for (int ks = 0; ks < 8; ks++) {
            unsigned a[2][4];
            #pragma unroll
            for (int mi = 0; mi < 2; mi++) {
                int r0 = (32 * w + 16 * mi + g) * FP + 8 * ks;
                int r1 = r0 + 8 * FP;
                a[mi][0] = Ps[r0 + t];     a[mi][1] = Ps[r1 + t];
                a[mi][2] = Ps[r0 + t + 4]; a[mi][3] = Ps[r1 + t + 4];
            }
            #pragma unroll
            for (int nf = 0; nf < 8; nf++) {
                unsigned b0 = Vb[(8 * ks + t) * FV + 8 * nf + g];
                unsigned b1 = Vb[(8 * ks + t + 4) * FV + 8 * nf + g];
                mma_tf32(o[0][nf], a[0][0], a[0][1], a[0][2], a[0][3], b0, b1);
                mma_tf32(o[1][nf], a[1][0], a[1][1], a[1][2], a[1][3], b0, b1);
            }
        }
        __syncwarp();
    }

    // epilogue: normalize -> tf32 -> concat-head write [m][h*64+e]
    const int b = bh >> 4, h = bh & 15;
    #pragma unroll
    for (int mi = 0; mi < 2; mi++) {
        float inv0 = 1.f / l_i[2 * mi], inv1 = 1.f / l_i[2 * mi + 1];
        int row = qrow0 + 32 * w + 16 * mi + g;
        #pragma unroll
        for (int nf = 0; nf < 8; nf++) {
            int e = 8 * nf + 2 * t;
            size_t i0 = ((size_t)(b * S_LEN + row)) * (HEADS * DH) + h * DH + e;
            size_t i1 = ((size_t)(b * S_LEN + row + 8)) * (HEADS * DH) + h * DH + e;
            *(uint2*)(g_attn + i0) =
                make_uint2(f2tf(o[mi][nf][0] * inv0), f2tf(o[mi][nf][1] * inv0));
            *(uint2*)(g_attn + i1) =
                make_uint2(f2tf(o[mi][nf][2] * inv1), f2tf(o[mi][nf][3] * inv1));
        }
    }
}

// ======================= Output projection =======================
#define OBM 128
#define OBK 32
#define OASTR 36
#define OBSTR 72

__global__ __launch_bounds__(256) void out_gemm(
    const float* __restrict__ bo, float* __restrict__ outp)
{
    __shared__ unsigned As[OBM * OASTR];
    __shared__ unsigned Bs[OBK * OBSTR];

    const int tid = threadIdx.x, w = tid >> 5, lane = tid & 31;
    const int g = lane >> 2, t = lane & 3;
    const int wm = w >> 1, wn = w & 1;
    const int m0 = blockIdx.x * OBM;

    float acc[2][4][4] = {};

    for (int k0 = 0; k0 < DIN; k0 += OBK) {
        __syncthreads();
        {
            int r = tid >> 3, kc = (tid & 7) * 4;
            #pragma unroll
            for (int it = 0; it < 4; it++) {
                int row = r + 32 * it;
                *(uint4*)&As[row * OASTR + kc] =
                    *(const uint4*)(g_attn + (size_t)(m0 + row) * DIN + k0 + kc);
            }
        }
        {
            int r = tid >> 4, n = (tid & 15) * 4;
            #pragma unroll
            for (int it = 0; it < 2; it++) {
                int row = r + 16 * it;
                *(uint4*)&Bs[row * OBSTR + n] =
                    *(const uint4*)(g_wo + (size_t)(k0 + row) * DH + n);
            }
        }
        __syncthreads();

        #pragma unroll
        for (int ks = 0; ks < 4; ks++) {
            unsigned a[2][4];
            #pragma unroll
            for (int mi = 0; mi < 2; mi++) {
                int r0 = (32 * wm + 16 * mi + g) * OASTR + 8 * ks;
                int r1 = r0 + 8 * OASTR;
                a[mi][0] = As[r0 + t];     a[mi][1] = As[r1 + t];
                a[mi][2] = As[r0 + t + 4]; a[mi][3] = As[r1 + t + 4];
            }
            #pragma unroll
            for (int nf = 0; nf < 4; nf++) {
                int n = 32 * wn + 8 * nf + g;
                unsigned b0 = Bs[(8 * ks + t) * OBSTR + n];
                unsigned b1 = Bs[(8 * ks + t + 4) * OBSTR + n];
                mma_tf32(acc[0][nf], a[0][0], a[0][1], a[0][2], a[0][3], b0, b1);
                mma_tf32(acc[1][nf], a[1][0], a[1][1], a[1][2], a[1][3], b0, b1);
            }
        }
    }

    #pragma unroll
    for (int mi = 0; mi < 2; mi++)
        #pragma unroll
        for (int nf = 0; nf < 4; nf++) {
            int e = 32 * wn + 8 * nf + 2 * t;
            float be0 = bo[e], be1 = bo[e + 1];
            int row = m0 + 32 * wm + 16 * mi + g;
            #pragma unroll
            for (int rr = 0; rr < 2; rr++) {
                int m = row + 8 * rr;
                *(float2*)(outp + (size_t)m * DH + e) =
                    make_float2(acc[mi][nf][2 * rr] + be0,
                                acc[mi][nf][2 * rr + 1] + be1);
            }
        }
}

// ======================= launch =======================
extern "C" void kernel_launch(void* const* d_in, const int* in_sizes, int n_in,
                              void* d_out, int out_size)
{
    const float* x  = (const float*)d_in[0];
    const float* Wq = (const float*)d_in[1];
    const float* bq = (const float*)d_in[2];
    const float* Wk = (const float*)d_in[3];
    const float* bk = (const float*)d_in[4];
    const float* Wv = (const float*)d_in[5];
    const float* bv = (const float*)d_in[6];
    const float* Wo = (const float*)d_in[7];
    const float* bo = (const float*)d_in[8];
    float* outp = (float*)d_out;

    cudaFuncSetAttribute(qkv_gemm,
                         cudaFuncAttributeMaxDynamicSharedMemorySize, QKV_SMEM);
    cudaFuncSetAttribute(flash_kernel,
                         cudaFuncAttributeMaxDynamicSharedMemorySize, ATT_SMEM);

    // device scratch addresses (host side)
    unsigned *p_xt, *p_wq, *p_wk, *p_wv, *p_wo;
    cudaGetSymbolAddress((void**)&p_xt, g_xt);
    cudaGetSymbolAddress((void**)&p_wq, g_wq);
    cudaGetSymbolAddress((void**)&p_wk, g_wk);
    cudaGetSymbolAddress((void**)&p_wv, g_wv);
    cudaGetSymbolAddress((void**)&p_wo, g_wo);

    const int NX = M_TOT * DIN / 4;        // 2097152
    const int NW = HEADS * DIN * DH / 4;   // 262144
    const int NO = DIN * DH / 4;           // 16384
    to_tf32_kernel<<<NX / 256, 256>>>((const float4*)x,  (uint4*)p_xt, NX);
    to_tf32_kernel<<<NW / 256, 256>>>((const float4*)Wq, (uint4*)p_wq, NW);
    to_tf32_kernel<<<NW / 256, 256>>>((const float4*)Wk, (uint4*)p_wk, NW);
    to_tf32_kernel<<<NW / 256, 256>>>((const float4*)Wv, (uint4*)p_wv, NW);
    to_tf32_kernel<<<NO / 256, 256>>>((const float4*)Wo, (uint4*)p_wo, NO);

    dim3 g1(M_TOT / QBM, HEADS / 2, 3);
    qkv_gemm<<<g1, 128, QKV_SMEM>>>(bq, bk, bv);

    dim3 g2(S_LEN / 128, BATCH * HEADS);
    flash_kernel<<<g2, 128, ATT_SMEM>>>();

    out_gemm<<<M_TOT / OBM, 256>>>(bo, outp);
}

// round 9
// speedup vs baseline: 2.0516x; 1.9219x over previous
#include <cuda_runtime.h>
#include <cuda_fp16.h>

#define S_LEN 2048
#define BATCH 4
#define HEADS 16
#define DH 64
#define DIN 1024
#define M_TOT (BATCH * S_LEN)  // 8192

// ---------------- scratch (allocation-free) — fp16 ----------------
__device__ __half g_xh[M_TOT * DIN];                 // x fp16
__device__ __half g_wqt[HEADS * DH * DIN];           // W^T fp16: [h][e][k]
__device__ __half g_wkt[HEADS * DH * DIN];
__device__ __half g_wvt[HEADS * DH * DIN];
__device__ __half g_wot[DH * DIN];                   // [n=64][k=1024]
__device__ __half g_q[BATCH * HEADS * S_LEN * DH];   // 1/8 scale folded
__device__ __half g_k[BATCH * HEADS * S_LEN * DH];
__device__ __half g_v[BATCH * HEADS * S_LEN * DH];   // natural [s][e]
__device__ __half g_attn[M_TOT * HEADS * DH];        // [m][h*64+e]

// ---------------- helpers ----------------
__device__ __forceinline__ unsigned packh2(float lo, float hi) {
    __half2 h = __floats2half2_rn(lo, hi);
    return *(unsigned*)&h;
}
__device__ __forceinline__ void mma_f16(float* c, const unsigned* a,
                                        unsigned b0, unsigned b1) {
    asm volatile(
        "mma.sync.aligned.m16n8k16.row.col.f32.f16.f16.f32 "
        "{%0,%1,%2,%3}, {%4,%5,%6,%7}, {%8,%9}, {%0,%1,%2,%3};\n"
        : "+f"(c[0]), "+f"(c[1]), "+f"(c[2]), "+f"(c[3])
        : "r"(a[0]), "r"(a[1]), "r"(a[2]), "r"(a[3]), "r"(b0), "r"(b1));
}
__device__ __forceinline__ void ldsm4(unsigned& r0, unsigned& r1,
                                      unsigned& r2, unsigned& r3, unsigned a) {
    asm volatile("ldmatrix.sync.aligned.m8n8.x4.shared.b16 {%0,%1,%2,%3}, [%4];"
                 : "=r"(r0), "=r"(r1), "=r"(r2), "=r"(r3) : "r"(a));
}
__device__ __forceinline__ void ldsm4t(unsigned& r0, unsigned& r1,
                                       unsigned& r2, unsigned& r3, unsigned a) {
    asm volatile("ldmatrix.sync.aligned.m8n8.x4.trans.shared.b16 {%0,%1,%2,%3}, [%4];"
                 : "=r"(r0), "=r"(r1), "=r"(r2), "=r"(r3) : "r"(a));
}
__device__ __forceinline__ void cp16(unsigned saddr, const void* gptr) {
    asm volatile("cp.async.ca.shared.global [%0], [%1], 16;\n"
                 :: "r"(saddr), "l"(gptr));
}
__device__ __forceinline__ unsigned saddr_of(const void* p) {
    return (unsigned)__cvta_generic_to_shared(p);
}
#define CP_COMMIT() asm volatile("cp.async.commit_group;\n" ::: "memory")
#define CP_WAIT0()  asm volatile("cp.async.wait_group 0;\n" ::: "memory")

// ======================= pre-convert =======================
__global__ __launch_bounds__(256) void x_to_h(
    const float4* __restrict__ src, uint2* __restrict__ dst, int n4)
{
    int i = blockIdx.x * blockDim.x + threadIdx.x;
    if (i < n4) {
        float4 v = src[i];
        dst[i] = make_uint2(packh2(v.x, v.y), packh2(v.z, v.w));
    }
}

// W [h][k=1024][e=64] fp32 -> Wt [h][e=64][k=1024] fp16. grid (16 ktiles, nh).
__global__ __launch_bounds__(256) void w_transpose(
    const float* __restrict__ W, __half* __restrict__ Wt)
{
    __shared__ float S[64][65];
    const int h = blockIdx.y, k0 = blockIdx.x * 64;
    const int tid = threadIdx.x;
    {
        int r = tid >> 2, e0 = (tid & 3) * 16;
        const float* src = W + ((size_t)h * DIN + k0 + r) * DH + e0;
        #pragma unroll
        for (int i = 0; i < 4; i++) {
            float4 v = *(const float4*)(src + 4 * i);
            S[r][e0 + 4 * i + 0] = v.x; S[r][e0 + 4 * i + 1] = v.y;
            S[r][e0 + 4 * i + 2] = v.z; S[r][e0 + 4 * i + 3] = v.w;
        }
    }
    __syncthreads();
    {
        int e = tid >> 2, c0 = (tid & 3) * 16;
        unsigned buf[8];
        #pragma unroll
        for (int i = 0; i < 8; i++)
            buf[i] = packh2(S[c0 + 2 * i][e], S[c0 + 2 * i + 1][e]);
        __half* dst = Wt + ((size_t)h * DH + e) * DIN + k0 + c0;
        *(uint4*)dst = make_uint4(buf[0], buf[1], buf[2], buf[3]);
        *(uint4*)(dst + 8) = make_uint4(buf[4], buf[5], buf[6], buf[7]);
    }
}

// ======================= QKV projection (fp16 mma + ldmatrix) ====================
// grid (64 m-tiles, 8 head-pairs, 3); block 256 (8 warps 4M x 2N), warp 32x64.
// Block tile 128m x 128n (2 heads), K-tile 64. A [128][K], B n-major [128][K].
#define STR 36                     // word stride (== 4 mod 32)
#define QA_W (128 * STR)           // 4608 words per buffer
#define QB_W (128 * STR)
#define QKV_SMEM ((QA_W + QB_W) * 2 * 4)   // 73728 B

__global__ __launch_bounds__(256, 2) void qkv_gemm(
    const float* __restrict__ bq, const float* __restrict__ bk,
    const float* __restrict__ bv)
{
    extern __shared__ unsigned qsm[];
    unsigned* As = qsm;                  // [2][128][36]
    unsigned* Bs = qsm + 2 * QA_W;       // [2][128][36]

    const int p = blockIdx.z, hp = blockIdx.y;
    const __half* Wt; const float* bias; __half* out; float sc;
    if (p == 0)      { Wt = g_wqt; bias = bq; out = g_q; sc = 0.125f; }
    else if (p == 1) { Wt = g_wkt; bias = bk; out = g_k; sc = 1.0f; }
    else             { Wt = g_wvt; bias = bv; out = g_v; sc = 1.0f; }

    const int tid = threadIdx.x, w = tid >> 5, lane = tid & 31;
    const int g = lane >> 2, t = lane & 3;
    const int wm = w >> 1, wn = w & 1;
    const int m0 = blockIdx.x * 128;

    // ldmatrix lane-derived offsets (words)
    const int a_row = lane & 15, a_kw = (lane >> 4) << 2;
    const int b_row = (lane & 7) | ((lane & 16) >> 1);
    const int b_kw  = (lane & 8) ? 4 : 0;

    // loaders: 128 rows x 64 halves, 2 threads/row, 4 cp16 each
    const int lr = tid >> 1, lc = (tid & 1) * 32;       // half offset
    const __half* xA = g_xh + (size_t)(m0 + lr) * DIN + lc;
    const __half* WB = Wt + ((size_t)(2 * hp + (lr >> 6)) * DH + (lr & 63)) * DIN + lc;

    const unsigned sA = saddr_of(As), sB = saddr_of(Bs);
    auto issue = [&](int k0, int buf) {
        unsigned da = sA + (buf * QA_W + lr * STR + (lc >> 1)) * 4;
        unsigned db = sB + (buf * QB_W + lr * STR + (lc >> 1)) * 4;
        #pragma unroll
        for (int i = 0; i < 4; i++) cp16(da + 16 * i, xA + k0 + 8 * i);
        #pragma unroll
        for (int i = 0; i < 4; i++) cp16(db + 16 * i, WB + k0 + 8 * i);
        CP_COMMIT();
    };

    const unsigned aoff = ((32 * wm + a_row) * STR + a_kw) * 4;
    const unsigned boff = ((64 * wn + b_row) * STR + b_kw) * 4;

    float acc[2][8][4] = {};
    const int NT = DIN / 64;   // 16

    issue(0, 0);
    for (int tt = 0; tt < NT; tt++) {
        CP_WAIT0();
        __syncthreads();
        if (tt + 1 < NT) issue((tt + 1) * 64, (tt + 1) & 1);

        unsigned ab = sA + (tt & 1) * QA_W * 4;
        unsigned bb = sB + (tt & 1) * QB_W * 4;
        #pragma unroll
        for (int ks = 0; ks < 4; ks++) {
            unsigned a[2][4];
            ldsm4(a[0][0], a[0][1], a[0][2], a[0][3], ab + aoff + 32 * ks);
            ldsm4(a[1][0], a[1][1], a[1][2], a[1][3],
                  ab + aoff + (16 * STR) * 4 + 32 * ks);
            #pragma unroll
            for (int nfp = 0; nfp < 4; nfp++) {
                unsigned b0, b1, b2, b3;
                ldsm4(b0, b1, b2, b3, bb + boff + (16 * nfp * STR) * 4 + 32 * ks);
                mma_f16(acc[0][2 * nfp],     a[0], b0, b1);
                mma_f16(acc[1][2 * nfp],     a[1], b0, b1);
                mma_f16(acc[0][2 * nfp + 1], a[0], b2, b3);
                mma_f16(acc[1][2 * nfp + 1], a[1], b2, b3);
            }
        }
    }

    // epilogue: bias (+Q scale) -> fp16 pairs -> scatter [B,H,S,64]
    const int head = 2 * hp + wn;
    const float* bp = bias + head * DH;
    #pragma unroll
    for (int mi = 0; mi < 2; mi++) {
        #pragma unroll
        for (int nf = 0; nf < 8; nf++) {
            int e = 8 * nf + 2 * t;
            float be0 = bp[e], be1 = bp[e + 1];
            int row = m0 + 32 * wm + 16 * mi + g;
            #pragma unroll
            for (int rr = 0; rr < 2; rr++) {
                int m = row + 8 * rr;
                int bb2 = m >> 11, s = m & 2047;
                size_t base = (((size_t)bb2 * HEADS + head) * S_LEN + s) * DH + e;
                *(unsigned*)(out + base) =
                    packh2((acc[mi][nf][2 * rr] + be0) * sc,
                           (acc[mi][nf][2 * rr + 1] + be1) * sc);
            }
        }
    }
}

// ======================= Flash attention (fp16 mma + ldmatrix) ===================
// grid (16 q-tiles, 64 bh); block 128 (4 warps x 32 q-rows). KV tile 64, dbl-buf.
#define K_W (64 * STR)     // 2304 words per buffer
#define V_W (64 * STR)
#define P_W (128 * STR)    // 4608
#define ATT_SMEM (((K_W + V_W) * 2 + P_W) * 4)   // 55296 B

__global__ __launch_bounds__(128, 2) void flash_kernel()
{
    extern __shared__ unsigned fsm[];
    unsigned* Ks = fsm;                     // [2][64][36]
    unsigned* Vs = fsm + 2 * K_W;           // [2][64][36] natural [kv][e]
    unsigned* Ps = fsm + 2 * (K_W + V_W);   // [128][36]; also Q staging

    const int tid = threadIdx.x, w = tid >> 5, lane = tid & 31;
    const int g = lane >> 2, t = lane & 3;
    const int qt = (int)(gridDim.x - 1 - blockIdx.x);
    const int bh = blockIdx.y;
    const size_t base = (size_t)bh * S_LEN * DH;
    const int qrow0 = qt * 128;

    const int a_row = lane & 15, a_kw = (lane >> 4) << 2;
    const int b_row = (lane & 7) | ((lane & 16) >> 1);
    const int b_kw  = (lane & 8) ? 4 : 0;
    const int v_row = lane & 15, v_ew = (lane & 16) >> 2;

    const unsigned sK = saddr_of(Ks), sV = saddr_of(Vs), sP = saddr_of(Ps);

    const int lr = tid >> 1, lc = (tid & 1) * 32;
    auto issue_kv = [&](int kt, int buf) {
        unsigned dk = sK + (buf * K_W + lr * STR + (lc >> 1)) * 4;
        unsigned dv = sV + (buf * V_W + lr * STR + (lc >> 1)) * 4;
        const __half* kg = g_k + base + (size_t)(kt * 64 + lr) * DH + lc;
        const __half* vg = g_v + base + (size_t)(kt * 64 + lr) * DH + lc;
        #pragma unroll
        for (int i = 0; i < 4; i++) cp16(dk + 16 * i, kg + 8 * i);
        #pragma unroll
        for (int i = 0; i < 4; i++) cp16(dv + 16 * i, vg + 8 * i);
        CP_COMMIT();
    };

    issue_kv(0, 0);
    // stage Q (fp16, scale folded) via cp.async into Ps
    {
        unsigned dq = sP + (tid * STR) * 4;
        const __half* qg = g_q + base + (size_t)(qrow0 + tid) * DH;
        #pragma unroll
        for (int i = 0; i < 8; i++) cp16(dq + 16 * i, qg + 8 * i);
        CP_COMMIT();
    }
    CP_WAIT0();
    __syncthreads();

    unsigned qf[2][4][4];
    #pragma unroll
    for (int mi = 0; mi < 2; mi++)
        #pragma unroll
        for (int ks = 0; ks < 4; ks++)
            ldsm4(qf[mi][ks][0], qf[mi][ks][1], qf[mi][ks][2], qf[mi][ks][3],
                  sP + (((32 * w + 16 * mi + a_row) * STR + a_kw) * 4) + 32 * ks);

    float m_i[4] = {-1e30f, -1e30f, -1e30f, -1e30f};
    float l_i[4] = {0.f, 0.f, 0.f, 0.f};
    float o[2][8][4] = {};

    const int ktmax = 2 * qt + 1;
    for (int kt = 0; kt <= ktmax; kt++) {
        if (kt > 0) { CP_WAIT0(); __syncthreads(); }
        if (kt < ktmax) issue_kv(kt + 1, (kt + 1) & 1);
        unsigned kb = sK + (kt & 1) * K_W * 4;
        unsigned vb = sV + (kt & 1) * V_W * 4;

        // S = Q K^T  (B-frags from n-major Ks rows = kv)
        float c_[2][8][4] = {};
        #pragma unroll
        for (int ks = 0; ks < 4; ks++) {
            #pragma unroll
            for (int nfp = 0; nfp < 4; nfp++) {
                unsigned b0, b1, b2, b3;
                ldsm4(b0, b1, b2, b3,
                      kb + (((16 * nfp + b_row) * STR + b_kw) * 4) + 32 * ks);
                mma_f16(c_[0][2 * nfp],     qf[0][ks], b0, b1);
                mma_f16(c_[1][2 * nfp],     qf[1][ks], b0, b1);
                mma_f16(c_[0][2 * nfp + 1], qf[0][ks], b2, b3);
                mma_f16(c_[1][2 * nfp + 1], qf[1][ks], b2, b3);
            }
        }

        // causal mask (diagonal-adjacent tiles only)
        if (kt >= 2 * qt) {
            int colbase = kt * 64;
            #pragma unroll
            for (int mi = 0; mi < 2; mi++) {
                int r0 = qrow0 + 32 * w + 16 * mi + g;
                #pragma unroll
                for (int nf = 0; nf < 8; nf++) {
                    int col = colbase + 8 * nf + 2 * t;
                    if (col     > r0)     c_[mi][nf][0] = -1e30f;
                    if (col + 1 > r0)     c_[mi][nf][1] = -1e30f;
                    if (col     > r0 + 8) c_[mi][nf][2] = -1e30f;
                    if (col + 1 > r0 + 8) c_[mi][nf][3] = -1e30f;
                }
            }
        }

        // online softmax
        float alpha[4];
        #pragma unroll
        for (int mi = 0; mi < 2; mi++)
            #pragma unroll
            for (int hh = 0; hh < 2; hh++) {
                int rr = 2 * mi + hh;
                float mx = -1e30f;
                #pragma unroll
                for (int nf = 0; nf < 8; nf++)
                    mx = fmaxf(mx, fmaxf(c_[mi][nf][2 * hh], c_[mi][nf][2 * hh + 1]));
                mx = fmaxf(mx, __shfl_xor_sync(0xffffffffu, mx, 1));
                mx = fmaxf(mx, __shfl_xor_sync(0xffffffffu, mx, 2));
                float m_new = fmaxf(m_i[rr], mx);
                alpha[rr] = __expf(m_i[rr] - m_new);
                float sum = 0.f;
                #pragma unroll
                for (int nf = 0; nf < 8; nf++) {
                    float p0 = __expf(c_[mi][nf][2 * hh] - m_new);
                    float p1 = __expf(c_[mi][nf][2 * hh + 1] - m_new);
                    c_[mi][nf][2 * hh] = p0; c_[mi][nf][2 * hh + 1] = p1;
                    sum += p0 + p1;
                }
                sum += __shfl_xor_sync(0xffffffffu, sum, 1);
                sum += __shfl_xor_sync(0xffffffffu, sum, 2);
                l_i[rr] = l_i[rr] * alpha[rr] + sum;
                m_i[rr] = m_new;
            }

        // stage P fp16 (warp-private rows) + rescale O
        #pragma unroll
        for (int mi = 0; mi < 2; mi++) {
            unsigned pr = sP + ((32 * w + 16 * mi + g) * STR) * 4;
            #pragma unroll
            for (int nf = 0; nf < 8; nf++) {
                int cw = (4 * nf + t) * 4;
                *(unsigned*)(size_t)0;  // placeholder removed below
            }
        }
        // (real P store)
        #pragma unroll
        for (int mi = 0; mi < 2; mi++) {
            int q0 = 32 * w + 16 * mi + g;
            #pragma unroll
            for (int nf = 0; nf < 8; nf++) {
                Ps[q0 * STR + 4 * nf + t] = packh2(c_[mi][nf][0], c_[mi][nf][1]);
                Ps[(q0 + 8) * STR + 4 * nf + t] = packh2(c_[mi][nf][2], c_[mi][nf][3]);
            }
        }
        #pragma unroll
        for (int mi = 0; mi < 2; mi++)
            #pragma unroll
            for (int nf = 0; nf < 8; nf++) {
                o[mi][nf][0] *= alpha[2 * mi];     o[mi][nf][1] *= alpha[2 * mi];
                o[mi][nf][2] *= alpha[2 * mi + 1]; o[mi][nf][3] *= alpha[2 * mi + 1];
            }
        __syncwarp();

        // O += P V   (A from Ps, B via ldmatrix.trans on natural V)
        #pragma unroll
        for (int ks = 0; ks < 4; ks++) {
            unsigned a[2][4];
            #pragma unroll
            for (int mi = 0; mi < 2; mi++)
                ldsm4(a[mi][0], a[mi][1], a[mi][2], a[mi][3],
                      sP + (((32 * w + 16 * mi + a_row) * STR + a_kw) * 4) + 32 * ks);
            #pragma unroll
            for (int nfp = 0; nfp < 4; nfp++) {
                unsigned b0, b1, b2, b3;
                ldsm4t(b0, b1, b2, b3,
                       vb + (((16 * ks + v_row) * STR + 8 * nfp + v_ew) * 4));
                mma_f16(o[0][2 * nfp],     a[0], b0, b1);
                mma_f16(o[1][2 * nfp],     a[1], b0, b1);
                mma_f16(o[0][2 * nfp + 1], a[0], b2, b3);
                mma_f16(o[1][2 * nfp + 1], a[1], b2, b3);
            }
        }
        __syncwarp();
    }

    // epilogue: normalize -> fp16 -> concat-head write [m][h*64+e]
    const int b = bh >> 4, h = bh & 15;
    #pragma unroll
    for (int mi = 0; mi < 2; mi++) {
        float inv0 = 1.f / l_i[2 * mi], inv1 = 1.f / l_i[2 * mi + 1];
        int row = qrow0 + 32 * w + 16 * mi + g;
        #pragma unroll
        for (int nf = 0; nf < 8; nf++) {
            int e = 8 * nf + 2 * t;
            size_t i0 = ((size_t)(b * S_LEN + row)) * (HEADS * DH) + h * DH + e;
            size_t i1 = ((size_t)(b * S_LEN + row + 8)) * (HEADS * DH) + h * DH + e;
            *(unsigned*)(g_attn + i0) = packh2(o[mi][nf][0] * inv0, o[mi][nf][1] * inv0);
            *(unsigned*)(g_attn + i1) = packh2(o[mi][nf][2] * inv1, o[mi][nf][3] * inv1);
        }
    }
}

// ======================= Output projection (fp16 mma + ldmatrix) =================
// [8192x1024] x [1024x64] + bo. grid 64; block 256 (8 warps 4M x 2N), warp 32x32.
#define OA_W (128 * STR)
#define OB_W (64 * STR)
#define OUT_SMEM ((OA_W + OB_W) * 2 * 4)   // 55296 B

__global__ __launch_bounds__(256, 2) void out_gemm(
    const float* __restrict__ bo, float* __restrict__ outp)
{
    extern __shared__ unsigned osm[];
    unsigned* As = osm;                 // [2][128][36]
    unsigned* Bs = osm + 2 * OA_W;      // [2][64][36]

    const int tid = threadIdx.x, w = tid >> 5, lane = tid & 31;
    const int g = lane >> 2, t = lane & 3;
    const int wm = w >> 1, wn = w & 1;
    const int m0 = blockIdx.x * 128;

    const int a_row = lane & 15, a_kw = (lane >> 4) << 2;
    const int b_row = (lane & 7) | ((lane & 16) >> 1);
    const int b_kw  = (lane & 8) ? 4 : 0;

    const unsigned sA = saddr_of(As), sB = saddr_of(Bs);
    const int lar = tid >> 1, lac = (tid & 1) * 32;
    const int lbr = tid >> 2, lbc = (tid & 3) * 16;
    const __half* xA = g_attn + (size_t)(m0 + lar) * DIN + lac;
    const __half* WB = g_wot + (size_t)lbr * DIN + lbc;

    auto issue = [&](int k0, int buf) {
        unsigned da = sA + (buf * OA_W + lar * STR + (lac >> 1)) * 4;
        unsigned db = sB + (buf * OB_W + lbr * STR + (lbc >> 1)) * 4;
        #pragma unroll
        for (int i = 0; i < 4; i++) cp16(da + 16 * i, xA + k0 + 8 * i);
        #pragma unroll
        for (int i = 0; i < 2; i++) cp16(db + 16 * i, WB + k0 + 8 * i);
        CP_COMMIT();
    };

    const unsigned aoff = ((32 * wm + a_row) * STR + a_kw) * 4;
    const unsigned boff = ((32 * wn + b_row) * STR + b_kw) * 4;

    float acc[2][4][4] = {};
    const int NT = DIN / 64;

    issue(0, 0);
    for (int tt = 0; tt < NT; tt++) {
        CP_WAIT0();
        __syncthreads();
        if (tt + 1 < NT) issue((tt + 1) * 64, (tt + 1) & 1);

        unsigned ab = sA + (tt & 1) * OA_W * 4;
        unsigned bb = sB + (tt & 1) * OB_W * 4;
        #pragma unroll
        for (int ks = 0; ks < 4; ks++) {
            unsigned a[2][4];
            ldsm4(a[0][0], a[0][1], a[0][2], a[0][3], ab + aoff + 32 * ks);
            ldsm4(a[1][0], a[1][1], a[1][2], a[1][3],
                  ab + aoff + (16 * STR) * 4 + 32 * ks);
            #pragma unroll
            for (int nfp = 0; nfp < 2; nfp++) {
                unsigned b0, b1, b2, b3;
                ldsm4(b0, b1, b2, b3, bb + boff + (16 * nfp * STR) * 4 + 32 * ks);
                mma_f16(acc[0][2 * nfp],     a[0], b0, b1);
                mma_f16(acc[1][2 * nfp],     a[1], b0, b1);
                mma_f16(acc[0][2 * nfp + 1], a[0], b2, b3);
                mma_f16(acc[1][2 * nfp + 1], a[1], b2, b3);
            }
        }
    }

    #pragma unroll
    for (int mi = 0; mi < 2; mi++)
        #pragma unroll
        for (int nf = 0; nf < 4; nf++) {
            int e = 32 * wn + 8 * nf + 2 * t;
            float be0 = bo[e], be1 = bo[e + 1];
            int row = m0 + 32 * wm + 16 * mi + g;
            #pragma unroll
            for (int rr = 0; rr < 2; rr++) {
                int m = row + 8 * rr;
                *(float2*)(outp + (size_t)m * DH + e) =
                    make_float2(acc[mi][nf][2 * rr] + be0,
                                acc[mi][nf][2 * rr + 1] + be1);
            }
        }
}

// ======================= launch =======================
extern "C" void kernel_launch(void* const* d_in, const int* in_sizes, int n_in,
                              void* d_out, int out_size)
{
    const float* x  = (const float*)d_in[0];
    const float* Wq = (const float*)d_in[1];
    const float* bq = (const float*)d_in[2];
    const float* Wk = (const float*)d_in[3];
    const float* bk = (const float*)d_in[4];
    const float* Wv = (const float*)d_in[5];
    const float* bv = (const float*)d_in[6];
    const float* Wo = (const float*)d_in[7];
    const float* bo = (const float*)d_in[8];
    float* outp = (float*)d_out;

    cudaFuncSetAttribute(qkv_gemm,
                         cudaFuncAttributeMaxDynamicSharedMemorySize, QKV_SMEM);
    cudaFuncSetAttribute(flash_kernel,
                         cudaFuncAttributeMaxDynamicSharedMemorySize, ATT_SMEM);
    cudaFuncSetAttribute(out_gemm,
                         cudaFuncAttributeMaxDynamicSharedMemorySize, OUT_SMEM);

    void *p_xh, *p_wqt, *p_wkt, *p_wvt, *p_wot;
    cudaGetSymbolAddress(&p_xh,  g_xh);
    cudaGetSymbolAddress(&p_wqt, g_wqt);
    cudaGetSymbolAddress(&p_wkt, g_wkt);
    cudaGetSymbolAddress(&p_wvt, g_wvt);
    cudaGetSymbolAddress(&p_wot, g_wot);

    const int NX4 = M_TOT * DIN / 4;
    x_to_h<<<NX4 / 256, 256>>>((const float4*)x, (uint2*)p_xh, NX4);
    w_transpose<<<dim3(DIN / 64, HEADS), 256>>>(Wq, (__half*)p_wqt);
    w_transpose<<<dim3(DIN / 64, HEADS), 256>>>(Wk, (__half*)p_wkt);
    w_transpose<<<dim3(DIN / 64, HEADS), 256>>>(Wv, (__half*)p_wvt);
    w_transpose<<<dim3(DIN / 64, 1), 256>>>(Wo, (__half*)p_wot);

    dim3 g1(M_TOT / 128, HEADS / 2, 3);
    qkv_gemm<<<g1, 256, QKV_SMEM>>>(bq, bk, bv);

    dim3 g2(S_LEN / 128, BATCH * HEADS);
    flash_kernel<<<g2, 128, ATT_SMEM>>>();

    out_gemm<<<M_TOT / 128, 256, OUT_SMEM>>>(bo, outp);
}

// round 10
// speedup vs baseline: 2.1575x; 1.0516x over previous
#include <cuda_runtime.h>
#include <cuda_fp16.h>

#define S_LEN 2048
#define BATCH 4
#define HEADS 16
#define DH 64
#define DIN 1024
#define M_TOT (BATCH * S_LEN)  // 8192

// ---------------- scratch (allocation-free) — fp16 ----------------
__device__ __half g_xh[M_TOT * DIN];                 // x fp16
__device__ __half g_wqt[HEADS * DH * DIN];           // W^T fp16: [h][e][k]
__device__ __half g_wkt[HEADS * DH * DIN];
__device__ __half g_wvt[HEADS * DH * DIN];
__device__ __half g_wot[DH * DIN];                   // [n=64][k=1024]
__device__ __half g_q[BATCH * HEADS * S_LEN * DH];   // 1/8 scale folded
__device__ __half g_k[BATCH * HEADS * S_LEN * DH];
__device__ __half g_v[BATCH * HEADS * S_LEN * DH];   // natural [s][e]
__device__ __half g_attn[M_TOT * HEADS * DH];        // [m][h*64+e]

// ---------------- helpers ----------------
__device__ __forceinline__ unsigned packh2(float lo, float hi) {
    __half2 h = __floats2half2_rn(lo, hi);
    return *(unsigned*)&h;
}
__device__ __forceinline__ void mma_f16(float* c, const unsigned* a,
                                        unsigned b0, unsigned b1) {
    asm volatile(
        "mma.sync.aligned.m16n8k16.row.col.f32.f16.f16.f32 "
        "{%0,%1,%2,%3}, {%4,%5,%6,%7}, {%8,%9}, {%0,%1,%2,%3};\n"
        : "+f"(c[0]), "+f"(c[1]), "+f"(c[2]), "+f"(c[3])
        : "r"(a[0]), "r"(a[1]), "r"(a[2]), "r"(a[3]), "r"(b0), "r"(b1));
}
__device__ __forceinline__ void ldsm4(unsigned& r0, unsigned& r1,
                                      unsigned& r2, unsigned& r3, unsigned a) {
    asm volatile("ldmatrix.sync.aligned.m8n8.x4.shared.b16 {%0,%1,%2,%3}, [%4];"
                 : "=r"(r0), "=r"(r1), "=r"(r2), "=r"(r3) : "r"(a));
}
__device__ __forceinline__ void ldsm4t(unsigned& r0, unsigned& r1,
                                       unsigned& r2, unsigned& r3, unsigned a) {
    asm volatile("ldmatrix.sync.aligned.m8n8.x4.trans.shared.b16 {%0,%1,%2,%3}, [%4];"
                 : "=r"(r0), "=r"(r1), "=r"(r2), "=r"(r3) : "r"(a));
}
__device__ __forceinline__ void cp16(unsigned saddr, const void* gptr) {
    asm volatile("cp.async.ca.shared.global [%0], [%1], 16;\n"
                 :: "r"(saddr), "l"(gptr));
}
__device__ __forceinline__ unsigned saddr_of(const void* p) {
    return (unsigned)__cvta_generic_to_shared(p);
}
#define CP_COMMIT() asm volatile("cp.async.commit_group;\n" ::: "memory")
#define CP_WAIT0()  asm volatile("cp.async.wait_group 0;\n" ::: "memory")

// ======================= pre-convert =======================
__global__ __launch_bounds__(256) void x_to_h(
    const float4* __restrict__ src, uint2* __restrict__ dst, int n4)
{
    int i = blockIdx.x * blockDim.x + threadIdx.x;
    if (i < n4) {
        float4 v = src[i];
        dst[i] = make_uint2(packh2(v.x, v.y), packh2(v.z, v.w));
    }
}

// W [h][k=1024][e=64] fp32 -> Wt [h][e=64][k=1024] fp16. grid (16 ktiles, nh).
__global__ __launch_bounds__(256) void w_transpose(
    const float* __restrict__ W, __half* __restrict__ Wt)
{
    __shared__ float S[64][65];
    const int h = blockIdx.y, k0 = blockIdx.x * 64;
    const int tid = threadIdx.x;
    {
        int r = tid >> 2, e0 = (tid & 3) * 16;
        const float* src = W + ((size_t)h * DIN + k0 + r) * DH + e0;
        #pragma unroll
        for (int i = 0; i < 4; i++) {
            float4 v = *(const float4*)(src + 4 * i);
            S[r][e0 + 4 * i + 0] = v.x; S[r][e0 + 4 * i + 1] = v.y;
            S[r][e0 + 4 * i + 2] = v.z; S[r][e0 + 4 * i + 3] = v.w;
        }
    }
    __syncthreads();
    {
        int e = tid >> 2, c0 = (tid & 3) * 16;
        unsigned buf[8];
        #pragma unroll
        for (int i = 0; i < 8; i++)
            buf[i] = packh2(S[c0 + 2 * i][e], S[c0 + 2 * i + 1][e]);
        __half* dst = Wt + ((size_t)h * DH + e) * DIN + k0 + c0;
        *(uint4*)dst = make_uint4(buf[0], buf[1], buf[2], buf[3]);
        *(uint4*)(dst + 8) = make_uint4(buf[4], buf[5], buf[6], buf[7]);
    }
}

// ======================= QKV projection (fp16 mma + ldmatrix) ====================
// grid (64 m-tiles, 8 head-pairs, 3); block 256 (8 warps 4M x 2N), warp 32x64.
// Block tile 128m x 128n (2 heads), K-tile 64. A [128][K], B n-major [128][K].
#define STR 36                     // word stride (== 4 mod 32)
#define QA_W (128 * STR)           // 4608 words per buffer
#define QB_W (128 * STR)
#define QKV_SMEM ((QA_W + QB_W) * 2 * 4)   // 73728 B

__global__ __launch_bounds__(256, 2) void qkv_gemm(
    const float* __restrict__ bq, const float* __restrict__ bk,
    const float* __restrict__ bv)
{
    extern __shared__ unsigned qsm[];
    unsigned* As = qsm;                  // [2][128][36]
    unsigned* Bs = qsm + 2 * QA_W;       // [2][128][36]

    const int p = blockIdx.z, hp = blockIdx.y;
    const __half* Wt; const float* bias; __half* out; float sc;
    if (p == 0)      { Wt = g_wqt; bias = bq; out = g_q; sc = 0.125f; }
    else if (p == 1) { Wt = g_wkt; bias = bk; out = g_k; sc = 1.0f; }
    else             { Wt = g_wvt; bias = bv; out = g_v; sc = 1.0f; }

    const int tid = threadIdx.x, w = tid >> 5, lane = tid & 31;
    const int g = lane >> 2, t = lane & 3;
    const int wm = w >> 1, wn = w & 1;
    const int m0 = blockIdx.x * 128;

    const int a_row = lane & 15, a_kw = (lane >> 4) << 2;
    const int b_row = (lane & 7) | ((lane & 16) >> 1);
    const int b_kw  = (lane & 8) ? 4 : 0;

    const int lr = tid >> 1, lc = (tid & 1) * 32;
    const __half* xA = g_xh + (size_t)(m0 + lr) * DIN + lc;
    const __half* WB = Wt + ((size_t)(2 * hp + (lr >> 6)) * DH + (lr & 63)) * DIN + lc;

    const unsigned sA = saddr_of(As), sB = saddr_of(Bs);
    auto issue = [&](int k0, int buf) {
        unsigned da = sA + (buf * QA_W + lr * STR + (lc >> 1)) * 4;
        unsigned db = sB + (buf * QB_W + lr * STR + (lc >> 1)) * 4;
        #pragma unroll
        for (int i = 0; i < 4; i++) cp16(da + 16 * i, xA + k0 + 8 * i);
        #pragma unroll
        for (int i = 0; i < 4; i++) cp16(db + 16 * i, WB + k0 + 8 * i);
        CP_COMMIT();
    };

    const unsigned aoff = ((32 * wm + a_row) * STR + a_kw) * 4;
    const unsigned boff = ((64 * wn + b_row) * STR + b_kw) * 4;

    float acc[2][8][4] = {};
    const int NT = DIN / 64;   // 16

    issue(0, 0);
    for (int tt = 0; tt < NT; tt++) {
        CP_WAIT0();
        __syncthreads();
        if (tt + 1 < NT) issue((tt + 1) * 64, (tt + 1) & 1);

        unsigned ab = sA + (tt & 1) * QA_W * 4;
        unsigned bb = sB + (tt & 1) * QB_W * 4;
        #pragma unroll
        for (int ks = 0; ks < 4; ks++) {
            unsigned a[2][4];
            ldsm4(a[0][0], a[0][1], a[0][2], a[0][3], ab + aoff + 32 * ks);
            ldsm4(a[1][0], a[1][1], a[1][2], a[1][3],
                  ab + aoff + (16 * STR) * 4 + 32 * ks);
            #pragma unroll
            for (int nfp = 0; nfp < 4; nfp++) {
                unsigned b0, b1, b2, b3;
                ldsm4(b0, b1, b2, b3, bb + boff + (16 * nfp * STR) * 4 + 32 * ks);
                mma_f16(acc[0][2 * nfp],     a[0], b0, b1);
                mma_f16(acc[1][2 * nfp],     a[1], b0, b1);
                mma_f16(acc[0][2 * nfp + 1], a[0], b2, b3);
                mma_f16(acc[1][2 * nfp + 1], a[1], b2, b3);
            }
        }
    }

    // epilogue: bias (+Q scale) -> fp16 pairs -> scatter [B,H,S,64]
    const int head = 2 * hp + wn;
    const float* bp = bias + head * DH;
    #pragma unroll
    for (int mi = 0; mi < 2; mi++) {
        #pragma unroll
        for (int nf = 0; nf < 8; nf++) {
            int e = 8 * nf + 2 * t;
            float be0 = bp[e], be1 = bp[e + 1];
            int row = m0 + 32 * wm + 16 * mi + g;
            #pragma unroll
            for (int rr = 0; rr < 2; rr++) {
                int m = row + 8 * rr;
                int bb2 = m >> 11, s = m & 2047;
                size_t base = (((size_t)bb2 * HEADS + head) * S_LEN + s) * DH + e;
                *(unsigned*)(out + base) =
                    packh2((acc[mi][nf][2 * rr] + be0) * sc,
                           (acc[mi][nf][2 * rr + 1] + be1) * sc);
            }
        }
    }
}

// ======================= Flash attention (fp16 mma, FA2 register-P) ==============
// grid (16 q-tiles, 64 bh); block 128 (4 warps x 32 q-rows). KV tile 64, dbl-buf.
// P passes from QK^T accumulators directly into PV A-fragments (no smem P).
#define K_W (64 * STR)     // 2304 words per buffer
#define V_W (64 * STR)
#define P_W (128 * STR)    // Q staging only
#define ATT_SMEM (((K_W + V_W) * 2 + P_W) * 4)   // 55296 B

__global__ __launch_bounds__(128, 2) void flash_kernel()
{
    extern __shared__ unsigned fsm[];
    unsigned* Ks = fsm;                     // [2][64][36]
    unsigned* Vs = fsm + 2 * K_W;           // [2][64][36] natural [kv][e]
    unsigned* Ps = fsm + 2 * (K_W + V_W);   // Q staging

    const int tid = threadIdx.x, w = tid >> 5, lane = tid & 31;
    const int g = lane >> 2, t = lane & 3;
    const int qt = (int)(gridDim.x - 1 - blockIdx.x);
    const int bh = blockIdx.y;
    const size_t base = (size_t)bh * S_LEN * DH;
    const int qrow0 = qt * 128;

    const int a_row = lane & 15, a_kw = (lane >> 4) << 2;
    const int b_row = (lane & 7) | ((lane & 16) >> 1);
    const int b_kw  = (lane & 8) ? 4 : 0;
    const int v_row = lane & 15, v_ew = (lane & 16) >> 2;

    const unsigned sK = saddr_of(Ks), sV = saddr_of(Vs), sP = saddr_of(Ps);

    const int lr = tid >> 1, lc = (tid & 1) * 32;
    auto issue_kv = [&](int kt, int buf) {
        unsigned dk = sK + (buf * K_W + lr * STR + (lc >> 1)) * 4;
        unsigned dv = sV + (buf * V_W + lr * STR + (lc >> 1)) * 4;
        const __half* kg = g_k + base + (size_t)(kt * 64 + lr) * DH + lc;
        const __half* vg = g_v + base + (size_t)(kt * 64 + lr) * DH + lc;
        #pragma unroll
        for (int i = 0; i < 4; i++) cp16(dk + 16 * i, kg + 8 * i);
        #pragma unroll
        for (int i = 0; i < 4; i++) cp16(dv + 16 * i, vg + 8 * i);
        CP_COMMIT();
    };

    issue_kv(0, 0);
    // stage Q (fp16, scale folded) via cp.async
    {
        unsigned dq = sP + (tid * STR) * 4;
        const __half* qg = g_q + base + (size_t)(qrow0 + tid) * DH;
        #pragma unroll
        for (int i = 0; i < 8; i++) cp16(dq + 16 * i, qg + 8 * i);
        CP_COMMIT();
    }
    CP_WAIT0();
    __syncthreads();

    unsigned qf[2][4][4];
    #pragma unroll
    for (int mi = 0; mi < 2; mi++)
        #pragma unroll
        for (int ks = 0; ks < 4; ks++)
            ldsm4(qf[mi][ks][0], qf[mi][ks][1], qf[mi][ks][2], qf[mi][ks][3],
                  sP + (((32 * w + 16 * mi + a_row) * STR + a_kw) * 4) + 32 * ks);

    float m_i[4] = {-1e30f, -1e30f, -1e30f, -1e30f};
    float l_i[4] = {0.f, 0.f, 0.f, 0.f};
    float o[2][8][4] = {};

    const int ktmax = 2 * qt + 1;
    for (int kt = 0; kt <= ktmax; kt++) {
        if (kt > 0) { CP_WAIT0(); __syncthreads(); }
        if (kt < ktmax) issue_kv(kt + 1, (kt + 1) & 1);
        unsigned kb = sK + (kt & 1) * K_W * 4;
        unsigned vb = sV + (kt & 1) * V_W * 4;

        // S = Q K^T
        float c_[2][8][4] = {};
        #pragma unroll
        for (int ks = 0; ks < 4; ks++) {
            #pragma unroll
            for (int nfp = 0; nfp < 4; nfp++) {
                unsigned b0, b1, b2, b3;
                ldsm4(b0, b1, b2, b3,
                      kb + (((16 * nfp + b_row) * STR + b_kw) * 4) + 32 * ks);
                mma_f16(c_[0][2 * nfp],     qf[0][ks], b0, b1);
                mma_f16(c_[1][2 * nfp],     qf[1][ks], b0, b1);
                mma_f16(c_[0][2 * nfp + 1], qf[0][ks], b2, b3);
                mma_f16(c_[1][2 * nfp + 1], qf[1][ks], b2, b3);
            }
        }

        // causal mask (diagonal-adjacent tiles only)
        if (kt >= 2 * qt) {
            int colbase = kt * 64;
            #pragma unroll
            for (int mi = 0; mi < 2; mi++) {
                int r0 = qrow0 + 32 * w + 16 * mi + g;
                #pragma unroll
                for (int nf = 0; nf < 8; nf++) {
                    int col = colbase + 8 * nf + 2 * t;
                    if (col     > r0)     c_[mi][nf][0] = -1e30f;
                    if (col + 1 > r0)     c_[mi][nf][1] = -1e30f;
                    if (col     > r0 + 8) c_[mi][nf][2] = -1e30f;
                    if (col + 1 > r0 + 8) c_[mi][nf][3] = -1e30f;
                }
            }
        }

        // online softmax (P stays in c_ registers)
        float alpha[4];
        #pragma unroll
        for (int mi = 0; mi < 2; mi++)
            #pragma unroll
            for (int hh = 0; hh < 2; hh++) {
                int rr = 2 * mi + hh;
                float mx = -1e30f;
                #pragma unroll
                for (int nf = 0; nf < 8; nf++)
                    mx = fmaxf(mx, fmaxf(c_[mi][nf][2 * hh], c_[mi][nf][2 * hh + 1]));
                mx = fmaxf(mx, __shfl_xor_sync(0xffffffffu, mx, 1));
                mx = fmaxf(mx, __shfl_xor_sync(0xffffffffu, mx, 2));
                float m_new = fmaxf(m_i[rr], mx);
                alpha[rr] = __expf(m_i[rr] - m_new);
                float sum = 0.f;
                #pragma unroll
                for (int nf = 0; nf < 8; nf++) {
                    float p0 = __expf(c_[mi][nf][2 * hh] - m_new);
                    float p1 = __expf(c_[mi][nf][2 * hh + 1] - m_new);
                    c_[mi][nf][2 * hh] = p0; c_[mi][nf][2 * hh + 1] = p1;
                    sum += p0 + p1;
                }
                sum += __shfl_xor_sync(0xffffffffu, sum, 1);
                sum += __shfl_xor_sync(0xffffffffu, sum, 2);
                l_i[rr] = l_i[rr] * alpha[rr] + sum;
                m_i[rr] = m_new;
            }

        // rescale O
        #pragma unroll
        for (int mi = 0; mi < 2; mi++)
            #pragma unroll
            for (int nf = 0; nf < 8; nf++) {
                o[mi][nf][0] *= alpha[2 * mi];     o[mi][nf][1] *= alpha[2 * mi];
                o[mi][nf][2] *= alpha[2 * mi + 1]; o[mi][nf][3] *= alpha[2 * mi + 1];
            }

        // O += P V — P packed from accumulator regs into A-fragments directly.
        // (m16n8k16 C-frag layout == fp16 A-frag layout for k-chunk pairing)
        #pragma unroll
        for (int ks = 0; ks < 4; ks++) {
            unsigned a[2][4];
            #pragma unroll
            for (int mi = 0; mi < 2; mi++) {
                a[mi][0] = packh2(c_[mi][2 * ks][0],     c_[mi][2 * ks][1]);
                a[mi][1] = packh2(c_[mi][2 * ks][2],     c_[mi][2 * ks][3]);
                a[mi][2] = packh2(c_[mi][2 * ks + 1][0], c_[mi][2 * ks + 1][1]);
                a[mi][3] = packh2(c_[mi][2 * ks + 1][2], c_[mi][2 * ks + 1][3]);
            }
            #pragma unroll
            for (int nfp = 0; nfp < 4; nfp++) {
                unsigned b0, b1, b2, b3;
                ldsm4t(b0, b1, b2, b3,
                       vb + (((16 * ks + v_row) * STR + 8 * nfp + v_ew) * 4));
                mma_f16(o[0][2 * nfp],     a[0], b0, b1);
                mma_f16(o[1][2 * nfp],     a[1], b0, b1);
                mma_f16(o[0][2 * nfp + 1], a[0], b2, b3);
                mma_f16(o[1][2 * nfp + 1], a[1], b2, b3);
            }
        }
    }

    // epilogue: normalize -> fp16 -> concat-head write [m][h*64+e]
    const int b = bh >> 4, h = bh & 15;
    #pragma unroll
    for (int mi = 0; mi < 2; mi++) {
        float inv0 = 1.f / l_i[2 * mi], inv1 = 1.f / l_i[2 * mi + 1];
        int row = qrow0 + 32 * w + 16 * mi + g;
        #pragma unroll
        for (int nf = 0; nf < 8; nf++) {
            int e = 8 * nf + 2 * t;
            size_t i0 = ((size_t)(b * S_LEN + row)) * (HEADS * DH) + h * DH + e;
            size_t i1 = ((size_t)(b * S_LEN + row + 8)) * (HEADS * DH) + h * DH + e;
            *(unsigned*)(g_attn + i0) = packh2(o[mi][nf][0] * inv0, o[mi][nf][1] * inv0);
            *(unsigned*)(g_attn + i1) = packh2(o[mi][nf][2] * inv1, o[mi][nf][3] * inv1);
        }
    }
}

// ======================= Output projection (fp16 mma + ldmatrix) =================
#define OA_W (128 * STR)
#define OB_W (64 * STR)
#define OUT_SMEM ((OA_W + OB_W) * 2 * 4)   // 55296 B

__global__ __launch_bounds__(256, 2) void out_gemm(
    const float* __restrict__ bo, float* __restrict__ outp)
{
    extern __shared__ unsigned osm[];
    unsigned* As = osm;                 // [2][128][36]
    unsigned* Bs = osm + 2 * OA_W;      // [2][64][36]

    const int tid = threadIdx.x, w = tid >> 5, lane = tid & 31;
    const int g = lane >> 2, t = lane & 3;
    const int wm = w >> 1, wn = w & 1;
    const int m0 = blockIdx.x * 128;

    const int a_row = lane & 15, a_kw = (lane >> 4) << 2;
    const int b_row = (lane & 7) | ((lane & 16) >> 1);
    const int b_kw  = (lane & 8) ? 4 : 0;

    const unsigned sA = saddr_of(As), sB = saddr_of(Bs);
    const int lar = tid >> 1, lac = (tid & 1) * 32;
    const int lbr = tid >> 2, lbc = (tid & 3) * 16;
    const __half* xA = g_attn + (size_t)(m0 + lar) * DIN + lac;
    const __half* WB = g_wot + (size_t)lbr * DIN + lbc;

    auto issue = [&](int k0, int buf) {
        unsigned da = sA + (buf * OA_W + lar * STR + (lac >> 1)) * 4;
        unsigned db = sB + (buf * OB_W + lbr * STR + (lbc >> 1)) * 4;
        #pragma unroll
        for (int i = 0; i < 4; i++) cp16(da + 16 * i, xA + k0 + 8 * i);
        #pragma unroll
        for (int i = 0; i < 2; i++) cp16(db + 16 * i, WB + k0 + 8 * i);
        CP_COMMIT();
    };

    const unsigned aoff = ((32 * wm + a_row) * STR + a_kw) * 4;
    const unsigned boff = ((32 * wn + b_row) * STR + b_kw) * 4;

    float acc[2][4][4] = {};
    const int NT = DIN / 64;

    issue(0, 0);
    for (int tt = 0; tt < NT; tt++) {
        CP_WAIT0();
        __syncthreads();
        if (tt + 1 < NT) issue((tt + 1) * 64, (tt + 1) & 1);

        unsigned ab = sA + (tt & 1) * OA_W * 4;
        unsigned bb = sB + (tt & 1) * OB_W * 4;
        #pragma unroll
        for (int ks = 0; ks < 4; ks++) {
            unsigned a[2][4];
            ldsm4(a[0][0], a[0][1], a[0][2], a[0][3], ab + aoff + 32 * ks);
            ldsm4(a[1][0], a[1][1], a[1][2], a[1][3],
                  ab + aoff + (16 * STR) * 4 + 32 * ks);
            #pragma unroll
            for (int nfp = 0; nfp < 2; nfp++) {
                unsigned b0, b1, b2, b3;
                ldsm4(b0, b1, b2, b3, bb + boff + (16 * nfp * STR) * 4 + 32 * ks);
                mma_f16(acc[0][2 * nfp],     a[0], b0, b1);
                mma_f16(acc[1][2 * nfp],     a[1], b0, b1);
                mma_f16(acc[0][2 * nfp + 1], a[0], b2, b3);
                mma_f16(acc[1][2 * nfp + 1], a[1], b2, b3);
            }
        }
    }

    #pragma unroll
    for (int mi = 0; mi < 2; mi++)
        #pragma unroll
        for (int nf = 0; nf < 4; nf++) {
            int e = 32 * wn + 8 * nf + 2 * t;
            float be0 = bo[e], be1 = bo[e + 1];
            int row = m0 + 32 * wm + 16 * mi + g;
            #pragma unroll
            for (int rr = 0; rr < 2; rr++) {
                int m = row + 8 * rr;
                *(float2*)(outp + (size_t)m * DH + e) =
                    make_float2(acc[mi][nf][2 * rr] + be0,
                                acc[mi][nf][2 * rr + 1] + be1);
            }
        }
}

// ======================= launch =======================
extern "C" void kernel_launch(void* const* d_in, const int* in_sizes, int n_in,
                              void* d_out, int out_size)
{
    const float* x  = (const float*)d_in[0];
    const float* Wq = (const float*)d_in[1];
    const float* bq = (const float*)d_in[2];
    const float* Wk = (const float*)d_in[3];
    const float* bk = (const float*)d_in[4];
    const float* Wv = (const float*)d_in[5];
    const float* bv = (const float*)d_in[6];
    const float* Wo = (const float*)d_in[7];
    const float* bo = (const float*)d_in[8];
    float* outp = (float*)d_out;

    cudaFuncSetAttribute(qkv_gemm,
                         cudaFuncAttributeMaxDynamicSharedMemorySize, QKV_SMEM);
    cudaFuncSetAttribute(flash_kernel,
                         cudaFuncAttributeMaxDynamicSharedMemorySize, ATT_SMEM);
    cudaFuncSetAttribute(out_gemm,
                         cudaFuncAttributeMaxDynamicSharedMemorySize, OUT_SMEM);

    void *p_xh, *p_wqt, *p_wkt, *p_wvt, *p_wot;
    cudaGetSymbolAddress(&p_xh,  g_xh);
    cudaGetSymbolAddress(&p_wqt, g_wqt);
    cudaGetSymbolAddress(&p_wkt, g_wkt);
    cudaGetSymbolAddress(&p_wvt, g_wvt);
    cudaGetSymbolAddress(&p_wot, g_wot);

    const int NX4 = M_TOT * DIN / 4;
    x_to_h<<<NX4 / 256, 256>>>((const float4*)x, (uint2*)p_xh, NX4);
    w_transpose<<<dim3(DIN / 64, HEADS), 256>>>(Wq, (__half*)p_wqt);
    w_transpose<<<dim3(DIN / 64, HEADS), 256>>>(Wk, (__half*)p_wkt);
    w_transpose<<<dim3(DIN / 64, HEADS), 256>>>(Wv, (__half*)p_wvt);
    w_transpose<<<dim3(DIN / 64, 1), 256>>>(Wo, (__half*)p_wot);

    dim3 g1(M_TOT / 128, HEADS / 2, 3);
    qkv_gemm<<<g1, 256, QKV_SMEM>>>(bq, bk, bv);

    dim3 g2(S_LEN / 128, BATCH * HEADS);
    flash_kernel<<<g2, 128, ATT_SMEM>>>();

    out_gemm<<<M_TOT / 128, 256, OUT_SMEM>>>(bo, outp);
}